// round 12
// baseline (speedup 1.0000x reference)
#include <cuda_runtime.h>

#define NB 32
#define GRID_N 128
#define CIN 32
#define COUT 32
#define TDIM 256
#define MM 17
#define KY_TOT 34   // 17 top rows + 17 bottom rows

typedef unsigned long long u64;

// packed f32x2 helpers (ptxas never emits FFMA2 from C++; PTX only)
__device__ __forceinline__ u64 ffma2(u64 a, u64 b, u64 c) {
    u64 d;
    asm("fma.rn.f32x2 %0, %1, %2, %3;" : "=l"(d) : "l"(a), "l"(b), "l"(c));
    return d;
}
__device__ __forceinline__ u64 pk2(float x, float y) {
    u64 v; asm("mov.b64 %0, {%1, %2};" : "=l"(v) : "f"(x), "f"(y)); return v;
}
__device__ __forceinline__ float2 upk2(u64 v) {
    float x, y; asm("mov.b64 {%0, %1}, %2;" : "=f"(x), "=f"(y) : "l"(v));
    return make_float2(x, y);
}

// Scratch (allocation-free): device globals.
__device__ float2 g_X1[NB * MM * GRID_N * CIN];   // [(b*17+kx)*128+y]*32+c
__device__ float2 g_Y1[NB * GRID_N * MM * COUT];  // [(b*128+y)*17+kx]*32+o
__device__ float2 g_TS[NB * KY_TOT];

// Twiddle tables, pre-packed for FFMA2 (signs/duplication baked in):
__device__ float4 g_T1v[9 * 63];      // K1:  (c0,-s0, c1,-s1) for kx pair (2p,2p+1|16)
__device__ float4 g_T2d[9 * 63 * 2];  // K2s1: even idx (c0,c0,s0,s0), odd (c1,c1,s1,s1)
__device__ float4 g_T3d[65 * 17];     // K2s3: [yy][m] (c,c,-s,s), mode p=m+1
__device__ float4 g_T3k[65 * 8];      // K3:  [xx][j] (cA,-sA, cB,-sB), modes 2j+1/2j+2

__global__ void k_tables() {
    int tid = blockIdx.x * blockDim.x + threadIdx.x;
    int stride = gridDim.x * blockDim.x;

    for (int i = tid; i < 9 * 63; i += stride) {
        int p = i / 63, xi = i - p * 63 + 1;
        int kx0 = 2 * p, kx1 = (p < 8) ? (2 * p + 1) : 16;
        float s0, c0, s1, c1;
        sincospif((float)(kx0 * xi) * (1.0f / 64.0f), &s0, &c0);
        sincospif((float)(kx1 * xi) * (1.0f / 64.0f), &s1, &c1);
        g_T1v[i] = make_float4(c0, -s0, c1, -s1);
    }
    for (int i = tid; i < 9 * 63; i += stride) {
        int q = i / 63, yy = i - q * 63 + 1;
        int g0 = 2 * q, g1 = (q < 8) ? (2 * q + 1) : 17;
        float s0, c0, s1, c1;
        sincospif((float)(g0 * yy) * (1.0f / 64.0f), &s0, &c0);
        sincospif((float)(g1 * yy) * (1.0f / 64.0f), &s1, &c1);
        g_T2d[2 * i]     = make_float4(c0, c0, s0, s0);
        g_T2d[2 * i + 1] = make_float4(c1, c1, s1, s1);
    }
    for (int i = tid; i < 65 * 17; i += stride) {
        int yy = i / 17, m = i - yy * 17;
        int p = m + 1;
        float s, c;
        sincospif((float)(p * yy) * (1.0f / 64.0f), &s, &c);
        g_T3d[i] = make_float4(c, c, -s, s);
    }
    for (int i = tid; i < 65 * 8; i += stride) {
        int xx = i >> 3, j = i & 7;
        float sA, cA, sB, cB;
        sincospif((float)((2 * j + 1) * xx) * (1.0f / 64.0f), &sA, &cA);
        sincospif((float)((2 * j + 2) * xx) * (1.0f / 64.0f), &sB, &cB);
        g_T3k[i] = make_float4(cA, -sA, cB, -sB);
    }
}

// ---------------------------------------------------------------------------
// K0: time-modulation scales  t1 = t_emb @ (k1r + i k1i), t2 likewise. (B,17)
// ---------------------------------------------------------------------------
__global__ void k0_tscale(const float* __restrict__ t_emb,
                          const float* __restrict__ k1r, const float* __restrict__ k1i,
                          const float* __restrict__ k2r, const float* __restrict__ k2i) {
    int b = blockIdx.x;
    int tid = threadIdx.x;           // 64 threads
    int which = tid >> 5;
    int m = tid & 31;
    if (m >= MM) return;
    const float* kr = which ? k2r : k1r;
    const float* ki = which ? k2i : k1i;
    const float* te = t_emb + b * TDIM;
    float ar = 0.f, ai = 0.f;
    #pragma unroll 4
    for (int d = 0; d < TDIM; ++d) {
        float v = te[d];
        ar += v * kr[d * MM + m];
        ai += v * ki[d * MM + m];
    }
    g_TS[b * KY_TOT + which * MM + m] = make_float2(ar, ai);
}

// ---------------------------------------------------------------------------
// K1: partial DFT over x (real input), 17 modes, scale 1/16384.
// Warp w computes kx pair (2w, 2w+1); FFMA2: acc=(ar,ai), data=(ve,vo) one
// LDS.64, table (c,-s) pairs. 2 FFMA2 per sample per mode-pair.
// ---------------------------------------------------------------------------
__global__ void __launch_bounds__(288) k1_dftx(const float* __restrict__ x) {
    __shared__ float2 sP[64 * CIN];    // (ve,vo); row0 = (xs0+xs64, xs0-xs64). 16KB
    __shared__ float4 T1v[9 * 63];     // 9.1KB
    int b = blockIdx.x >> 7, y = blockIdx.x & 127;
    int tid = threadIdx.x;

    const float* xrow = x + (size_t)(b * GRID_N + y) * GRID_N * CIN;
    for (int i = tid; i < 64 * CIN; i += 288) {
        int xi = i >> 5, c = i & 31;
        int xp = (xi == 0) ? 64 : (128 - xi);
        float a  = xrow[xi * CIN + c];
        float bb = xrow[xp * CIN + c];
        sP[i] = make_float2(a + bb, a - bb);
    }
    for (int i = tid; i < 9 * 63; i += 288) T1v[i] = g_T1v[i];
    __syncthreads();

    const float scale = 1.0f / 16384.0f;
    int w = tid >> 5, c = tid & 31;     // w 0..8
    float2 p0 = sP[c];
    u64 acc0 = pk2(p0.x, 0.f);          // kx even: +xs64 fold
    u64 acc1 = pk2(p0.y, 0.f);          // kx odd:  -xs64 fold
    const ulonglong2* T = (const ulonglong2*)&T1v[w * 63];
    const u64* P = (const u64*)&sP[CIN + c];
    #pragma unroll 7
    for (int j = 0; j < 63; ++j) {
        ulonglong2 tw = T[j];           // warp-uniform broadcast
        u64 pv = P[j * CIN];            // (ve, vo) @ xi=j+1
        acc0 = ffma2(pv, tw.x, acc0);
        acc1 = ffma2(pv, tw.y, acc1);
    }
    float2 r0 = upk2(acc0), r1 = upk2(acc1);
    g_X1[((b * MM + 2 * w) * GRID_N + y) * CIN + c] =
        make_float2(r0.x * scale, r0.y * scale);
    if (w < 8)
        g_X1[((b * MM + 2 * w + 1) * GRID_N + y) * CIN + c] =
            make_float2(r1.x * scale, r1.y * scale);
}

// ---------------------------------------------------------------------------
// K2 (fused, dynamic smem, 288 threads): per (b, kx):
//  stage1: paired DFT over y (FFMA2, duplicated tables); warp q does g-pair
//          (2q, 2q+1), each g emits rows (g, 34-g).
//  stage2: complex 32x32 channel mix + time scale (scalar)
//  stage3: paired inverse DFT (FFMA2), two yy share SD loads.
// smem layout (bytes):
//  [0,32768)       phase A: PA float4[64*32] = (ae.re, ae.im, ao.IM, ao.RE)
//                  phase B aliases: sZ float2[34*32]@0 (8704),
//                                   sSD float4[17*32]@8704 (8704) = (S.re,S.im,D.im,D.re)
//  [32768,50912)   Ttab: phase A = T2d (18144); phase B = T3d (17680, copied in stage 2)
//  [50912,59616)   sX2 float2[34*32]
//  [59616,59888)   sT float2[34]
// ---------------------------------------------------------------------------
#define K2_SMEM_BYTES 59888

__global__ void __launch_bounds__(288) k2_mid(
        const float* __restrict__ w1r, const float* __restrict__ w1i,
        const float* __restrict__ w2r, const float* __restrict__ w2i) {
    extern __shared__ char smemraw[];
    float4* PA   = (float4*)(smemraw);
    float4* Ttab = (float4*)(smemraw + 32768);
    float2* sX2  = (float2*)(smemraw + 50912);
    float2* sT   = (float2*)(smemraw + 59616);
    float2* sZ   = (float2*)(smemraw);           // phase B
    float4* sSD  = (float4*)(smemraw + 8704);    // phase B

    int b  = blockIdx.x / MM;
    int kx = blockIdx.x % MM;
    int tid = threadIdx.x;

    const float2* src = g_X1 + (size_t)(b * MM + kx) * GRID_N * CIN;
    for (int i = tid; i < 64 * CIN; i += 288) {
        int yy = i >> 5, c = i & 31;
        int yp = (yy == 0) ? 64 : (128 - yy);
        float2 a = src[yy * CIN + c];
        float2 d = src[yp * CIN + c];
        // hi half SWAPPED: (ao.im, ao.re) for FFMA2 lane order
        PA[i] = make_float4(a.x + d.x, a.y + d.y, a.y - d.y, a.x - d.x);
    }
    for (int i = tid; i < 9 * 63 * 2; i += 288) Ttab[i] = g_T2d[i];
    if (tid < KY_TOT) sT[tid] = g_TS[b * KY_TOT + tid];
    __syncthreads();

    // ---- stage 1: warp q -> g-pair (2q, 2q+1); each g -> rows (g, 34-g) ----
    {
        int q = tid >> 5, c = tid & 31;      // q 0..8
        int g0 = 2 * q;
        int g1 = (q < 8) ? (g0 + 1) : 17;
        const ulonglong2* Td = (const ulonglong2*)&Ttab[q * 63 * 2];
        const ulonglong2* P  = (const ulonglong2*)&PA[CIN + c];
        u64 a13 = 0, a24 = 0, b13 = 0, b24 = 0;
        #pragma unroll 3
        for (int j = 0; j < 63; ++j) {
            ulonglong2 p  = P[j * CIN];      // lo=(ae.re,ae.im) hi=(ao.im,ao.re)
            ulonglong2 tA = Td[2 * j];       // (c0,c0),(s0,s0)
            ulonglong2 tB = Td[2 * j + 1];   // (c1,c1),(s1,s1)
            a13 = ffma2(p.x, tA.x, a13);  a24 = ffma2(p.y, tA.y, a24);
            b13 = ffma2(p.x, tB.x, b13);  b24 = ffma2(p.y, tB.y, b24);
        }
        float2 u13 = upk2(a13), u24 = upk2(a24);
        float2 v13 = upk2(b13), v24 = upk2(b24);
        float4 p0 = PA[c];   // (ae.re, ae.im, ao.im, ao.re) @ yy=0 fold
        // g0 even: base (p0.x, p0.y)
        sX2[g0 * CIN + c] = make_float2(p0.x + u13.x + u24.x, p0.y + u13.y - u24.y);
        if (g0 >= 1)
            sX2[(34 - g0) * CIN + c] =
                make_float2(p0.x + u13.x - u24.x, p0.y + u13.y + u24.y);
        // g1 odd: base (ao.re, ao.im) = (p0.w, p0.z)
        if (g1 <= 16)
            sX2[g1 * CIN + c] = make_float2(p0.w + v13.x + v24.x, p0.z + v13.y - v24.y);
        sX2[(34 - g1) * CIN + c] =
            make_float2(p0.w + v13.x - v24.x, p0.z + v13.y + v24.y);
    }
    __syncthreads();

    // ---- stage 2: complex channel mix + time scale -> sZ (aliases PA) ----
    for (int idx = tid; idx < KY_TOT * COUT; idx += 288) {
        int kyi = idx >> 5, o = idx & 31;
        const float* wr; const float* wi; int iw;
        if (kyi < MM) { wr = w1r; wi = w1i; iw = kyi; }
        else          { wr = w2r; wi = w2i; iw = kyi - MM; }
        size_t base = ((size_t)(iw * MM + kx) * CIN) * COUT + o;
        float ar = 0.f, ai = 0.f;
        #pragma unroll 8
        for (int c = 0; c < CIN; ++c) {
            float2 a = sX2[kyi * CIN + c];
            float wre = wr[base + (size_t)c * COUT];
            float wim = wi[base + (size_t)c * COUT];
            ar += a.x * wre - a.y * wim;
            ai += a.x * wim + a.y * wre;
        }
        float2 ts = sT[kyi];
        sZ[idx] = make_float2(ar * ts.x - ai * ts.y, ar * ts.y + ai * ts.x);
    }
    // stage-3 table into Ttab region (T2d dead after stage 1)
    for (int i = tid; i < 65 * 17; i += 288) Ttab[i] = g_T3d[i];
    __syncthreads();

    // ---- S/D mode pairs: (S.re, S.im, D.im, D.re); p=17 self-paired ----
    for (int i = tid; i < MM * 32; i += 288) {
        int p = (i >> 5) + 1, o = i & 31;
        float2 zp = sZ[p * COUT + o];
        float4 sd;
        if (p < MM) {
            float2 zq = sZ[(34 - p) * COUT + o];
            sd = make_float4(zp.x + zq.x, zp.y + zq.y, zp.y - zq.y, zp.x - zq.x);
        } else {
            sd = make_float4(zp.x, zp.y, -zp.y, -zp.x);
        }
        sSD[i] = sd;
    }
    __syncthreads();

    // ---- stage 3: two yy share SD loads; Y[y]=E+F, Y[128-y]=E-F ----
    {
        int o = tid & 31, q = tid >> 5;      // q 0..8
        u64 z0 = *(const u64*)&sZ[o];
        const ulonglong2* SD = ((const ulonglong2*)sSD) + o;
        const ulonglong2* T3 = (const ulonglong2*)Ttab;
        for (int yb = q * 2; yb <= 64; yb += 18) {
            int y2ok = (yb + 1 <= 64);
            const ulonglong2* Ta = T3 + yb * 17;
            const ulonglong2* Tb = y2ok ? (T3 + (yb + 1) * 17) : Ta;
            u64 e1 = z0, f1 = 0, e2 = z0, f2 = 0;
            #pragma unroll 4
            for (int m = 0; m < 17; ++m) {
                ulonglong2 sd = SD[m * 32];  // lo=(S.re,S.im) hi=(D.im,D.re)
                ulonglong2 wA = Ta[m];       // (c,c),(-s,s)
                e1 = ffma2(sd.x, wA.x, e1);
                f1 = ffma2(sd.y, wA.y, f1);
                ulonglong2 wB = Tb[m];
                e2 = ffma2(sd.x, wB.x, e2);
                f2 = ffma2(sd.y, wB.y, f2);
            }
            float2 E1 = upk2(e1), F1 = upk2(f1);
            float2 E2 = upk2(e2), F2 = upk2(f2);
            size_t rb = ((size_t)b * GRID_N) * MM * COUT + (size_t)kx * COUT + o;
            g_Y1[rb + (size_t)yb * MM * COUT] = make_float2(E1.x + F1.x, E1.y + F1.y);
            if (yb >= 1 && yb < 64)
                g_Y1[rb + (size_t)(128 - yb) * MM * COUT] =
                    make_float2(E1.x - F1.x, E1.y - F1.y);
            if (y2ok) {
                int y2 = yb + 1;
                g_Y1[rb + (size_t)y2 * MM * COUT] =
                    make_float2(E2.x + F2.x, E2.y + F2.y);
                g_Y1[rb + (size_t)(128 - y2) * MM * COUT] =
                    make_float2(E2.x - F2.x, E2.y - F2.y);
            }
        }
    }
}

// ---------------------------------------------------------------------------
// K3: inverse over x (irfft C2R), FFMA2 with acc=(E,O), spectra pre-packed
// into registers (reused across 9 xx iterations), two accumulator chains.
//   out[x] = E+O, out[128-x] = E-O
// ---------------------------------------------------------------------------
__global__ void __launch_bounds__(256) k3_idftx(float* __restrict__ out) {
    __shared__ float2 sY[MM * COUT];   // 4.25 KB
    __shared__ float4 T3[65 * 8];      // (c,-s) pairs for modes 2j+1, 2j+2
    int b = blockIdx.x >> 7, y = blockIdx.x & 127;
    int tid = threadIdx.x;

    const float2* src = g_Y1 + (size_t)(b * GRID_N + y) * MM * COUT;
    for (int i = tid; i < MM * COUT; i += 256) sY[i] = src[i];
    for (int i = tid; i < 65 * 8; i += 256) T3[i] = g_T3k[i];
    __syncthreads();

    int o  = tid & 31;
    int xg = tid >> 5;   // 0..7

    u64 yp[16];
    u64 acc0 = pk2(sY[o].x, 0.f);   // mode 0: Im ignored (C2R); bin 64 zero
    #pragma unroll
    for (int k = 1; k < MM; ++k) {
        float2 v = sY[k * COUT + o];
        yp[k - 1] = pk2(2.f * v.x, 2.f * v.y);
    }

    float* orow = out + (size_t)(b * GRID_N + y) * GRID_N * COUT;
    for (int xx = xg; xx <= 64; xx += 8) {
        u64 accA = acc0, accB = 0;      // two chains for latency
        const ulonglong2* T = (const ulonglong2*)&T3[xx * 8];
        #pragma unroll
        for (int j = 0; j < 8; ++j) {
            ulonglong2 tw = T[j];       // warp-uniform broadcast
            accA = ffma2(yp[2 * j],     tw.x, accA);
            accB = ffma2(yp[2 * j + 1], tw.y, accB);
        }
        float2 A = upk2(accA), B = upk2(accB);
        float E = A.x + B.x, O = A.y + B.y;
        orow[(size_t)xx * COUT + o] = E + O;
        if (xx >= 1 && xx < 64)
            orow[(size_t)(128 - xx) * COUT + o] = E - O;
    }
}

// ---------------------------------------------------------------------------
extern "C" void kernel_launch(void* const* d_in, const int* in_sizes, int n_in,
                              void* d_out, int out_size) {
    const float* x     = (const float*)d_in[0];
    const float* t_emb = (const float*)d_in[1];
    const float* w1r   = (const float*)d_in[2];
    const float* w1i   = (const float*)d_in[3];
    const float* w2r   = (const float*)d_in[4];
    const float* w2i   = (const float*)d_in[5];
    const float* k1r   = (const float*)d_in[6];
    const float* k1i   = (const float*)d_in[7];
    const float* k2r   = (const float*)d_in[8];
    const float* k2i   = (const float*)d_in[9];
    float* out = (float*)d_out;

    cudaFuncSetAttribute(k2_mid, cudaFuncAttributeMaxDynamicSharedMemorySize,
                         K2_SMEM_BYTES);

    k_tables <<<32, 256>>>();
    k0_tscale<<<NB, 64>>>(t_emb, k1r, k1i, k2r, k2i);
    k1_dftx  <<<NB * GRID_N, 288>>>(x);
    k2_mid   <<<NB * MM, 288, K2_SMEM_BYTES>>>(w1r, w1i, w2r, w2i);
    k3_idftx <<<NB * GRID_N, 256>>>(out);
}

// round 13
// speedup vs baseline: 1.1838x; 1.1838x over previous
#include <cuda_runtime.h>

#define NB 32
#define GRID_N 128
#define CIN 32
#define COUT 32
#define TDIM 256
#define MM 17
#define KY_TOT 34   // 17 top rows + 17 bottom rows

// Scratch (allocation-free): device globals.
__device__ float2 g_X1[NB * MM * GRID_N * CIN];   // [(b*17+kx)*128+y]*32+c
__device__ float2 g_Y1[NB * GRID_N * MM * COUT];  // [(b*128+y)*17+kx]*32+o
__device__ float2 g_TS[NB * KY_TOT];

// Precomputed twiddle tables (built once per launch in k0_setup).
__device__ float4 g_T1v[9 * 63];    // K1:  [pair][xi-1] = (c,s)@kx=2p, (c,s)@kx=2p+1 (p=8: 16,16)
__device__ float4 g_T2v[9 * 63];    // K2s1:[pair][yy-1] = (c,s)@g=2q, (c,s)@g=2q+1 (q=8: 16,17)
__device__ float4 g_T2b[65 * 9];    // K2s3:[yy][j] modes 2j+1 / 2j+2 (j=8: mode 17)
__device__ float4 g_T3 [65 * 8];    // K3:  [xx][j] modes 2j+1 / 2j+2

// ---------------------------------------------------------------------------
// K0 (merged): twiddle tables (all threads, grid-strided) + time-modulation
// scales t1/t2 (tid<64). 32 blocks x 256 threads.
// ---------------------------------------------------------------------------
__global__ void k0_setup(const float* __restrict__ t_emb,
                         const float* __restrict__ k1r, const float* __restrict__ k1i,
                         const float* __restrict__ k2r, const float* __restrict__ k2i) {
    int gtid = blockIdx.x * blockDim.x + threadIdx.x;
    int stride = gridDim.x * blockDim.x;

    for (int i = gtid; i < 9 * 63; i += stride) {
        int p = i / 63, xi = i - p * 63 + 1;
        int kx0 = 2 * p, kx1 = (p < 8) ? (2 * p + 1) : 16;
        float s0, c0, s1, c1;
        sincospif((float)(kx0 * xi) * (1.0f / 64.0f), &s0, &c0);
        sincospif((float)(kx1 * xi) * (1.0f / 64.0f), &s1, &c1);
        g_T1v[i] = make_float4(c0, s0, c1, s1);
    }
    for (int i = gtid; i < 9 * 63; i += stride) {
        int q = i / 63, yy = i - q * 63 + 1;
        int g0 = 2 * q, g1 = (q < 8) ? (2 * q + 1) : 17;
        float s0, c0, s1, c1;
        sincospif((float)(g0 * yy) * (1.0f / 64.0f), &s0, &c0);
        sincospif((float)(g1 * yy) * (1.0f / 64.0f), &s1, &c1);
        g_T2v[i] = make_float4(c0, s0, c1, s1);
    }
    for (int i = gtid; i < 65 * 9; i += stride) {
        int yy = i / 9, j = i - yy * 9;
        float s1, c1, s2 = 0.f, c2 = 0.f;
        int p1 = (j < 8) ? (2 * j + 1) : 17;
        sincospif((float)(p1 * yy) * (1.0f / 64.0f), &s1, &c1);
        if (j < 8) sincospif((float)((2 * j + 2) * yy) * (1.0f / 64.0f), &s2, &c2);
        g_T2b[i] = make_float4(c1, s1, c2, s2);
    }
    for (int i = gtid; i < 65 * 8; i += stride) {
        int xx = i >> 3, j = i & 7;
        float sA, cA, sB, cB;
        sincospif((float)((2 * j + 1) * xx) * (1.0f / 64.0f), &sA, &cA);
        sincospif((float)((2 * j + 2) * xx) * (1.0f / 64.0f), &sB, &cB);
        g_T3[i] = make_float4(cA, sA, cB, sB);
    }

    // time-modulation scales: tid<64 per block, b = blockIdx.x
    int tid = threadIdx.x;
    if (tid < 64) {
        int b = blockIdx.x;
        int which = tid >> 5;
        int m = tid & 31;
        if (m < MM) {
            const float* kr = which ? k2r : k1r;
            const float* ki = which ? k2i : k1i;
            const float* te = t_emb + b * TDIM;
            float ar = 0.f, ai = 0.f;
            #pragma unroll 8
            for (int d = 0; d < TDIM; ++d) {
                float v = te[d];
                ar += v * kr[d * MM + m];
                ai += v * ki[d * MM + m];
            }
            g_TS[b * KY_TOT + which * MM + m] = make_float2(ar, ai);
        }
    }
}

// ---------------------------------------------------------------------------
// K1: partial DFT over x (real input), 17 modes, scale 1/16384.
// 288 threads = 9 warps; warp w computes kx pair (2w, 2w+1) — each LDS.64
// data load feeds 4 FMAs (2 modes). Perfectly balanced: 1 item/thread.
// ---------------------------------------------------------------------------
__global__ void __launch_bounds__(288) k1_dftx(const float* __restrict__ x) {
    __shared__ float2 sP[64 * CIN];    // (ve,vo); row0 = (xs0+xs64, xs0-xs64). 16KB
    __shared__ float4 T1v[9 * 63];     // 9.1KB
    int b = blockIdx.x >> 7, y = blockIdx.x & 127;
    int tid = threadIdx.x;

    const float* xrow = x + (size_t)(b * GRID_N + y) * GRID_N * CIN;
    for (int i = tid; i < 64 * CIN; i += 288) {
        int xi = i >> 5, c = i & 31;
        int xp = (xi == 0) ? 64 : (128 - xi);
        float a  = xrow[xi * CIN + c];
        float bb = xrow[xp * CIN + c];
        sP[i] = make_float2(a + bb, a - bb);
    }
    for (int i = tid; i < 9 * 63; i += 288) T1v[i] = g_T1v[i];
    __syncthreads();

    const float scale = 1.0f / 16384.0f;
    int w = tid >> 5, c = tid & 31;     // w 0..8
    int kx0 = 2 * w;
    float2 p0 = sP[c];
    float ar0 = p0.x, ai0 = 0.f;        // kx0 even -> +xs64 fold
    float ar1 = p0.y, ai1 = 0.f;        // kx1 odd  -> -xs64 fold (w=8: discarded)
    const float4* T = &T1v[w * 63];
    const float2* P = &sP[CIN + c];
    #pragma unroll 7
    for (int j = 0; j < 63; ++j) {
        float4 tw = T[j];               // warp-uniform broadcast (both modes)
        float2 p  = P[j * CIN];         // xi = j+1
        ar0 += p.x * tw.x;  ai0 -= p.y * tw.y;
        ar1 += p.x * tw.z;  ai1 -= p.y * tw.w;
    }
    g_X1[((b * MM + kx0) * GRID_N + y) * CIN + c] =
        make_float2(ar0 * scale, ai0 * scale);
    if (w < 8)
        g_X1[((b * MM + kx0 + 1) * GRID_N + y) * CIN + c] =
            make_float2(ar1 * scale, ai1 * scale);
}

// ---------------------------------------------------------------------------
// K2 (fused, dynamic smem, 288 threads): per (b, kx):
//  stage1: paired DFT over y; warp q computes g-pair (2q, 2q+1), both modes'
//          twiddles in ONE float4 broadcast; each g emits rows (g, 34-g).
//  stage2: complex 32x32 channel mix + time scale (unroll 16 for MLP)
//  stage3: paired inverse DFT, TWO yy per iteration sharing the SD loads.
// ---------------------------------------------------------------------------
// dynamic smem (bytes):
//  [0,32768)      phase A: PA float4[64*32]  (ae.re, ae.im, ao.re, ao.im)
//                 phase B aliases: sZ  float2[34*32] @0      (8704)
//                                  sSD float4[17*32] @8704   (8704)
//                                  T3p float4[65*9]  @17408  (9360)
//  [32768,41984)  T2v float4[9*63] (9072 used)
//  [41984,50688)  sX2 float2[34*32]
//  [50688,50960)  sT  float2[34]
#define K2_SMEM_BYTES 50960

__global__ void __launch_bounds__(288) k2_mid(
        const float* __restrict__ w1r, const float* __restrict__ w1i,
        const float* __restrict__ w2r, const float* __restrict__ w2i) {
    extern __shared__ char smemraw[];
    float4* PA  = (float4*)(smemraw);
    float4* T2v = (float4*)(smemraw + 32768);
    float2* sX2 = (float2*)(smemraw + 41984);
    float2* sT  = (float2*)(smemraw + 50688);
    float2* sZ  = (float2*)(smemraw);            // phase B
    float4* sSD = (float4*)(smemraw + 8704);     // [p-1][o]: (S.re,S.im,D.re,D.im)
    float4* T3p = (float4*)(smemraw + 17408);    // [yy][j]

    int b  = blockIdx.x / MM;
    int kx = blockIdx.x % MM;
    int tid = threadIdx.x;

    const float2* src = g_X1 + (size_t)(b * MM + kx) * GRID_N * CIN;
    for (int i = tid; i < 64 * CIN; i += 288) {
        int yy = i >> 5, c = i & 31;
        int yp = (yy == 0) ? 64 : (128 - yy);
        float2 a = src[yy * CIN + c];
        float2 d = src[yp * CIN + c];
        PA[i] = make_float4(a.x + d.x, a.y + d.y, a.x - d.x, a.y - d.y);
    }
    for (int i = tid; i < 9 * 63; i += 288) T2v[i] = g_T2v[i];
    if (tid < KY_TOT) sT[tid] = g_TS[b * KY_TOT + tid];
    __syncthreads();

    // ---- stage 1: warp q computes g-pair (2q, 2q+1); each g -> rows (g,34-g)
    {
        int q = tid >> 5, c = tid & 31;      // q 0..8
        int g0 = 2 * q;
        int g1 = (q < 8) ? (g0 + 1) : 17;
        const float4* T = &T2v[q * 63];
        const float4* P = &PA[CIN + c];
        float a1 = 0.f, a2 = 0.f, a3 = 0.f, a4 = 0.f;   // g0
        float b1 = 0.f, b2 = 0.f, b3 = 0.f, b4 = 0.f;   // g1
        #pragma unroll 3
        for (int j = 0; j < 63; ++j) {
            float4 w = T[j];                 // (c0,s0,c1,s1) broadcast
            float4 p = P[j * CIN];           // yy = j+1
            a1 += p.x * w.x;  a2 += p.w * w.y;
            a3 += p.y * w.x;  a4 += p.z * w.y;
            b1 += p.x * w.z;  b2 += p.w * w.w;
            b3 += p.y * w.z;  b4 += p.z * w.w;
        }
        float4 p0 = PA[c];
        // g0 (even): base = (p0.x, p0.y)
        sX2[g0 * CIN + c] = make_float2(p0.x + a1 + a2, p0.y + a3 - a4);
        if (g0 >= 1)
            sX2[(34 - g0) * CIN + c] = make_float2(p0.x + a1 - a2, p0.y + a3 + a4);
        // g1 (odd): base = (p0.z, p0.w)
        if (g1 <= 16)
            sX2[g1 * CIN + c] = make_float2(p0.z + b1 + b2, p0.w + b3 - b4);
        sX2[(34 - g1) * CIN + c] = make_float2(p0.z + b1 - b2, p0.w + b3 + b4);
    }
    __syncthreads();

    // ---- stage 2: complex channel mix + time scale -> sZ (aliases PA) ----
    for (int idx = tid; idx < KY_TOT * COUT; idx += 288) {
        int kyi = idx >> 5, o = idx & 31;
        const float* wr; const float* wi; int iw;
        if (kyi < MM) { wr = w1r; wi = w1i; iw = kyi; }
        else          { wr = w2r; wi = w2i; iw = kyi - MM; }
        size_t base = ((size_t)(iw * MM + kx) * CIN) * COUT + o;
        float ar = 0.f, ai = 0.f;
        #pragma unroll 16
        for (int c = 0; c < CIN; ++c) {
            float2 a = sX2[kyi * CIN + c];
            float wre = wr[base + (size_t)c * COUT];
            float wim = wi[base + (size_t)c * COUT];
            ar += a.x * wre - a.y * wim;
            ai += a.x * wim + a.y * wre;
        }
        float2 ts = sT[kyi];
        sZ[idx] = make_float2(ar * ts.x - ai * ts.y, ar * ts.y + ai * ts.x);
    }
    // stage-3 packed table (aliases dead PA region, disjoint from sZ/sSD)
    for (int i = tid; i < 65 * 9; i += 288) T3p[i] = g_T2b[i];
    __syncthreads();

    // ---- S/D mode pairs: modes p=1..16 pair with (34-p); p=17 unpaired ----
    for (int i = tid; i < MM * 32; i += 288) {
        int p = (i >> 5) + 1, o = i & 31;
        float2 zp = sZ[p * COUT + o];
        float4 sd;
        if (p < MM) {
            float2 zq = sZ[(34 - p) * COUT + o];
            sd = make_float4(zp.x + zq.x, zp.y + zq.y, zp.x - zq.x, zp.y - zq.y);
        } else {
            sd = make_float4(zp.x, zp.y, -zp.x, -zp.y);
        }
        sSD[i] = sd;
    }
    __syncthreads();

    // ---- stage 3: TWO yy per iteration share SD loads; Y[y]=E+F, Y[128-y]=E-F
    {
        int o = tid & 31, q = tid >> 5;      // q 0..8
        float2 z0 = sZ[o];
        const float4* SD = &sSD[o];
        for (int yb = q * 2; yb <= 64; yb += 18) {
            int y2ok = (yb + 1 <= 64);
            const float4* Ta = &T3p[yb * 9];
            const float4* Tb = y2ok ? &T3p[(yb + 1) * 9] : Ta;
            float er1 = z0.x, ei1 = z0.y, fr1 = 0.f, fi1 = 0.f;
            float er2 = z0.x, ei2 = z0.y, fr2 = 0.f, fi2 = 0.f;
            #pragma unroll 2
            for (int j = 0; j < 8; ++j) {
                float4 a  = SD[(2 * j) * 32];
                float4 b2 = SD[(2 * j + 1) * 32];
                float4 wA = Ta[j];
                er1 += a.x * wA.x;   ei1 += a.y * wA.x;
                fr1 -= a.w * wA.y;   fi1 += a.z * wA.y;
                er1 += b2.x * wA.z;  ei1 += b2.y * wA.z;
                fr1 -= b2.w * wA.w;  fi1 += b2.z * wA.w;
                float4 wB = Tb[j];
                er2 += a.x * wB.x;   ei2 += a.y * wB.x;
                fr2 -= a.w * wB.y;   fi2 += a.z * wB.y;
                er2 += b2.x * wB.z;  ei2 += b2.y * wB.z;
                fr2 -= b2.w * wB.w;  fi2 += b2.z * wB.w;
            }
            {   // mode 17
                float4 a  = SD[16 * 32];
                float4 wA = Ta[8];
                er1 += a.x * wA.x;  ei1 += a.y * wA.x;
                fr1 -= a.w * wA.y;  fi1 += a.z * wA.y;
                float4 wB = Tb[8];
                er2 += a.x * wB.x;  ei2 += a.y * wB.x;
                fr2 -= a.w * wB.y;  fi2 += a.z * wB.y;
            }
            size_t rb = ((size_t)b * GRID_N) * MM * COUT + (size_t)kx * COUT + o;
            g_Y1[rb + (size_t)yb * MM * COUT] = make_float2(er1 + fr1, ei1 + fi1);
            if (yb >= 1 && yb < 64)
                g_Y1[rb + (size_t)(128 - yb) * MM * COUT] =
                    make_float2(er1 - fr1, ei1 - fi1);
            if (y2ok) {
                int y2 = yb + 1;                   // 1..63 -> both outputs
                g_Y1[rb + (size_t)y2 * MM * COUT] = make_float2(er2 + fr2, ei2 + fi2);
                g_Y1[rb + (size_t)(128 - y2) * MM * COUT] =
                    make_float2(er2 - fr2, ei2 - fi2);
            }
        }
    }
}

// ---------------------------------------------------------------------------
// K3: inverse over x (irfft C2R), output pairing. 512 threads = TWO y-rows
// per block; each 256-thread half runs the R11 per-row code (same registers),
// sharing one twiddle-table copy. out[x] = E+O, out[128-x] = E-O.
// ---------------------------------------------------------------------------
__global__ void __launch_bounds__(512) k3_idftx(float* __restrict__ out) {
    __shared__ float2 sY[2][MM * COUT];  // 8.5 KB
    __shared__ float4 T3[65 * 8];        // 8.3 KB, shared by both halves
    int b = blockIdx.x >> 6, yp = blockIdx.x & 63;
    int tid = threadIdx.x;
    int h = tid >> 8;                    // half 0/1 -> row 2*yp + h
    int t = tid & 255;
    int y = 2 * yp + h;

    const float2* src = g_Y1 + (size_t)(b * GRID_N + y) * MM * COUT;
    for (int i = t; i < MM * COUT; i += 256) sY[h][i] = src[i];
    for (int i = tid; i < 65 * 8; i += 512) T3[i] = g_T3[i];
    __syncthreads();

    int o  = t & 31;
    int xg = t >> 5;   // 0..7

    float yr[MM], yi[MM];
    yr[0] = sY[h][o].x;   // Im of bin 0 ignored (C2R); bin 64 is zero
    yi[0] = 0.f;
    #pragma unroll
    for (int k = 1; k < MM; ++k) {
        float2 v = sY[h][k * COUT + o];
        yr[k] = 2.f * v.x;
        yi[k] = 2.f * v.y;
    }

    float* orow = out + (size_t)(b * GRID_N + y) * GRID_N * COUT;
    for (int xx = xg; xx <= 64; xx += 8) {
        float E = yr[0], O = 0.f;
        const float4* T = &T3[xx * 8];
        #pragma unroll
        for (int j = 0; j < 8; ++j) {
            float4 w = T[j];            // warp-uniform broadcast, imm offsets
            int ka = 2 * j + 1, kb = 2 * j + 2;
            E += yr[ka] * w.x;  O -= yi[ka] * w.y;
            E += yr[kb] * w.z;  O -= yi[kb] * w.w;
        }
        orow[(size_t)xx * COUT + o] = E + O;
        if (xx >= 1 && xx < 64)
            orow[(size_t)(128 - xx) * COUT + o] = E - O;
    }
}

// ---------------------------------------------------------------------------
extern "C" void kernel_launch(void* const* d_in, const int* in_sizes, int n_in,
                              void* d_out, int out_size) {
    const float* x     = (const float*)d_in[0];
    const float* t_emb = (const float*)d_in[1];
    const float* w1r   = (const float*)d_in[2];
    const float* w1i   = (const float*)d_in[3];
    const float* w2r   = (const float*)d_in[4];
    const float* w2i   = (const float*)d_in[5];
    const float* k1r   = (const float*)d_in[6];
    const float* k1i   = (const float*)d_in[7];
    const float* k2r   = (const float*)d_in[8];
    const float* k2i   = (const float*)d_in[9];
    float* out = (float*)d_out;

    cudaFuncSetAttribute(k2_mid, cudaFuncAttributeMaxDynamicSharedMemorySize,
                         K2_SMEM_BYTES);

    k0_setup<<<NB, 256>>>(t_emb, k1r, k1i, k2r, k2i);
    k1_dftx <<<NB * GRID_N, 288>>>(x);
    k2_mid  <<<NB * MM, 288, K2_SMEM_BYTES>>>(w1r, w1i, w2r, w2i);
    k3_idftx<<<NB * 64, 512>>>(out);
}

// round 15
// speedup vs baseline: 1.2679x; 1.0710x over previous
#include <cuda_runtime.h>

#define NB 32
#define GRID_N 128
#define CIN 32
#define COUT 32
#define TDIM 256
#define MM 17
#define KY_TOT 34   // 17 top rows + 17 bottom rows

// Scratch (allocation-free): device globals.
__device__ float2 g_X1[NB * MM * GRID_N * CIN];   // [(b*17+kx)*128+y]*32+c
__device__ float2 g_Y1[NB * GRID_N * MM * COUT];  // [(b*128+y)*17+kx]*32+o
__device__ float2 g_TS[NB * KY_TOT];

// Precomputed twiddle tables (built once per launch in k0_setup).
__device__ float4 g_T1v[9 * 63];    // K1:  [pair][xi-1] = (c,s)@kx=2p, (c,s)@kx=2p+1 (p=8: 16,16)
__device__ float4 g_T2v[9 * 63];    // K2s1:[pair][yy-1] = (c,s)@g=2q, (c,s)@g=2q+1 (q=8: 16,17)
__device__ float4 g_T2b[65 * 9];    // K2s3:[yy][j] modes 2j+1 / 2j+2 (j=8: mode 17)
__device__ float4 g_T3 [65 * 8];    // K3:  [xx][j] modes 2j+1 / 2j+2

// ---------------------------------------------------------------------------
// K0 (merged): twiddle tables (grid-strided) + time-modulation scales (tid<64).
// ---------------------------------------------------------------------------
__global__ void k0_setup(const float* __restrict__ t_emb,
                         const float* __restrict__ k1r, const float* __restrict__ k1i,
                         const float* __restrict__ k2r, const float* __restrict__ k2i) {
    int gtid = blockIdx.x * blockDim.x + threadIdx.x;
    int stride = gridDim.x * blockDim.x;

    for (int i = gtid; i < 9 * 63; i += stride) {
        int p = i / 63, xi = i - p * 63 + 1;
        int kx0 = 2 * p, kx1 = (p < 8) ? (2 * p + 1) : 16;
        float s0, c0, s1, c1;
        sincospif((float)(kx0 * xi) * (1.0f / 64.0f), &s0, &c0);
        sincospif((float)(kx1 * xi) * (1.0f / 64.0f), &s1, &c1);
        g_T1v[i] = make_float4(c0, s0, c1, s1);
    }
    for (int i = gtid; i < 9 * 63; i += stride) {
        int q = i / 63, yy = i - q * 63 + 1;
        int g0 = 2 * q, g1 = (q < 8) ? (2 * q + 1) : 17;
        float s0, c0, s1, c1;
        sincospif((float)(g0 * yy) * (1.0f / 64.0f), &s0, &c0);
        sincospif((float)(g1 * yy) * (1.0f / 64.0f), &s1, &c1);
        g_T2v[i] = make_float4(c0, s0, c1, s1);
    }
    for (int i = gtid; i < 65 * 9; i += stride) {
        int yy = i / 9, j = i - yy * 9;
        float s1, c1, s2 = 0.f, c2 = 0.f;
        int p1 = (j < 8) ? (2 * j + 1) : 17;
        sincospif((float)(p1 * yy) * (1.0f / 64.0f), &s1, &c1);
        if (j < 8) sincospif((float)((2 * j + 2) * yy) * (1.0f / 64.0f), &s2, &c2);
        g_T2b[i] = make_float4(c1, s1, c2, s2);
    }
    for (int i = gtid; i < 65 * 8; i += stride) {
        int xx = i >> 3, j = i & 7;
        float sA, cA, sB, cB;
        sincospif((float)((2 * j + 1) * xx) * (1.0f / 64.0f), &sA, &cA);
        sincospif((float)((2 * j + 2) * xx) * (1.0f / 64.0f), &sB, &cB);
        g_T3[i] = make_float4(cA, sA, cB, sB);
    }

    int tid = threadIdx.x;
    if (tid < 64) {
        int b = blockIdx.x;
        int which = tid >> 5;
        int m = tid & 31;
        if (m < MM) {
            const float* kr = which ? k2r : k1r;
            const float* ki = which ? k2i : k1i;
            const float* te = t_emb + b * TDIM;
            float ar = 0.f, ai = 0.f;
            #pragma unroll 8
            for (int d = 0; d < TDIM; ++d) {
                float v = te[d];
                ar += v * kr[d * MM + m];
                ai += v * ki[d * MM + m];
            }
            g_TS[b * KY_TOT + which * MM + m] = make_float2(ar, ai);
        }
    }
}

// ---------------------------------------------------------------------------
// K1: partial DFT over x (real input), 17 modes, scale 1/16384.
// 288 threads = 9 warps; warp w computes kx pair (2w, 2w+1) — each LDS.64
// data load feeds 4 FMAs (2 modes). Perfectly balanced: 1 item/thread.
// ---------------------------------------------------------------------------
__global__ void __launch_bounds__(288) k1_dftx(const float* __restrict__ x) {
    __shared__ float2 sP[64 * CIN];    // (ve,vo); row0 = (xs0+xs64, xs0-xs64). 16KB
    __shared__ float4 T1v[9 * 63];     // 9.1KB
    int b = blockIdx.x >> 7, y = blockIdx.x & 127;
    int tid = threadIdx.x;

    const float* xrow = x + (size_t)(b * GRID_N + y) * GRID_N * CIN;
    for (int i = tid; i < 64 * CIN; i += 288) {
        int xi = i >> 5, c = i & 31;
        int xp = (xi == 0) ? 64 : (128 - xi);
        float a  = xrow[xi * CIN + c];
        float bb = xrow[xp * CIN + c];
        sP[i] = make_float2(a + bb, a - bb);
    }
    for (int i = tid; i < 9 * 63; i += 288) T1v[i] = g_T1v[i];
    __syncthreads();

    const float scale = 1.0f / 16384.0f;
    int w = tid >> 5, c = tid & 31;     // w 0..8
    int kx0 = 2 * w;
    float2 p0 = sP[c];
    float ar0 = p0.x, ai0 = 0.f;        // kx0 even -> +xs64 fold
    float ar1 = p0.y, ai1 = 0.f;        // kx1 odd  -> -xs64 fold (w=8: discarded)
    const float4* T = &T1v[w * 63];
    const float2* P = &sP[CIN + c];
    #pragma unroll 7
    for (int j = 0; j < 63; ++j) {
        float4 tw = T[j];               // warp-uniform broadcast (both modes)
        float2 p  = P[j * CIN];         // xi = j+1
        ar0 += p.x * tw.x;  ai0 -= p.y * tw.y;
        ar1 += p.x * tw.z;  ai1 -= p.y * tw.w;
    }
    g_X1[((b * MM + kx0) * GRID_N + y) * CIN + c] =
        make_float2(ar0 * scale, ai0 * scale);
    if (w < 8)
        g_X1[((b * MM + kx0 + 1) * GRID_N + y) * CIN + c] =
            make_float2(ar1 * scale, ai1 * scale);
}

// ---------------------------------------------------------------------------
// K2 (fused, dynamic smem, 288 threads): per (b, kx):
//  stage1: paired DFT over y; warp q computes g-pair (2q, 2q+1).
//  stage2: complex 32x32 channel mix + time scale. OUTPUT-PAIRED: each item
//          computes (o, o+1), weights loaded as float2 (LDG.64) — halves the
//          LSU issue count and the max-path item count (2 vs 4).
//  stage3: paired inverse DFT, TWO yy per iteration sharing the SD loads.
// ---------------------------------------------------------------------------
// dynamic smem (bytes):
//  [0,32768)      phase A: PA float4[64*32]  (ae.re, ae.im, ao.re, ao.im)
//                 phase B aliases: sZ  float2[34*32] @0      (8704)
//                                  sSD float4[17*32] @8704   (8704)
//                                  T3p float4[65*9]  @17408  (9360)
//  [32768,41984)  T2v float4[9*63] (9072 used)
//  [41984,50688)  sX2 float2[34*32]
//  [50688,50960)  sT  float2[34]
#define K2_SMEM_BYTES 50960

__global__ void __launch_bounds__(288) k2_mid(
        const float* __restrict__ w1r, const float* __restrict__ w1i,
        const float* __restrict__ w2r, const float* __restrict__ w2i) {
    extern __shared__ char smemraw[];
    float4* PA  = (float4*)(smemraw);
    float4* T2v = (float4*)(smemraw + 32768);
    float2* sX2 = (float2*)(smemraw + 41984);
    float2* sT  = (float2*)(smemraw + 50688);
    float2* sZ  = (float2*)(smemraw);            // phase B
    float4* sSD = (float4*)(smemraw + 8704);     // [p-1][o]: (S.re,S.im,D.re,D.im)
    float4* T3p = (float4*)(smemraw + 17408);    // [yy][j]

    int b  = blockIdx.x / MM;
    int kx = blockIdx.x % MM;
    int tid = threadIdx.x;

    const float2* src = g_X1 + (size_t)(b * MM + kx) * GRID_N * CIN;
    for (int i = tid; i < 64 * CIN; i += 288) {
        int yy = i >> 5, c = i & 31;
        int yp = (yy == 0) ? 64 : (128 - yy);
        float2 a = src[yy * CIN + c];
        float2 d = src[yp * CIN + c];
        PA[i] = make_float4(a.x + d.x, a.y + d.y, a.x - d.x, a.y - d.y);
    }
    for (int i = tid; i < 9 * 63; i += 288) T2v[i] = g_T2v[i];
    if (tid < KY_TOT) sT[tid] = g_TS[b * KY_TOT + tid];
    __syncthreads();

    // ---- stage 1: warp q computes g-pair (2q, 2q+1); each g -> rows (g,34-g)
    {
        int q = tid >> 5, c = tid & 31;      // q 0..8
        int g0 = 2 * q;
        int g1 = (q < 8) ? (g0 + 1) : 17;
        const float4* T = &T2v[q * 63];
        const float4* P = &PA[CIN + c];
        float a1 = 0.f, a2 = 0.f, a3 = 0.f, a4 = 0.f;   // g0
        float b1 = 0.f, b2 = 0.f, b3 = 0.f, b4 = 0.f;   // g1
        #pragma unroll 3
        for (int j = 0; j < 63; ++j) {
            float4 w = T[j];                 // (c0,s0,c1,s1) broadcast
            float4 p = P[j * CIN];           // yy = j+1
            a1 += p.x * w.x;  a2 += p.w * w.y;
            a3 += p.y * w.x;  a4 += p.z * w.y;
            b1 += p.x * w.z;  b2 += p.w * w.w;
            b3 += p.y * w.z;  b4 += p.z * w.w;
        }
        float4 p0 = PA[c];
        // g0 (even): base = (p0.x, p0.y)
        sX2[g0 * CIN + c] = make_float2(p0.x + a1 + a2, p0.y + a3 - a4);
        if (g0 >= 1)
            sX2[(34 - g0) * CIN + c] = make_float2(p0.x + a1 - a2, p0.y + a3 + a4);
        // g1 (odd): base = (p0.z, p0.w)
        if (g1 <= 16)
            sX2[g1 * CIN + c] = make_float2(p0.z + b1 + b2, p0.w + b3 - b4);
        sX2[(34 - g1) * CIN + c] = make_float2(p0.z + b1 - b2, p0.w + b3 + b4);
    }
    __syncthreads();

    // ---- stage 2: channel mix + time scale, OUTPUT-PAIRED (o, o+1) ----
    for (int idx = tid; idx < KY_TOT * 16; idx += 288) {
        int kyi = idx >> 4, op = (idx & 15) * 2;
        const float* wr; const float* wi; int iw;
        if (kyi < MM) { wr = w1r; wi = w1i; iw = kyi; }
        else          { wr = w2r; wi = w2i; iw = kyi - MM; }
        size_t base = ((size_t)(iw * MM + kx) * CIN) * COUT + op;
        const float2* wr2 = (const float2*)(wr + base);   // stride 16 float2 per c
        const float2* wi2 = (const float2*)(wi + base);
        float ar0 = 0.f, ai0 = 0.f, ar1 = 0.f, ai1 = 0.f;
        #pragma unroll 8
        for (int c = 0; c < CIN; ++c) {
            float2 a   = sX2[kyi * CIN + c];
            float2 wre = wr2[c * 16];        // LDG.64: weights for o, o+1
            float2 wim = wi2[c * 16];
            ar0 += a.x * wre.x - a.y * wim.x;
            ai0 += a.x * wim.x + a.y * wre.x;
            ar1 += a.x * wre.y - a.y * wim.y;
            ai1 += a.x * wim.y + a.y * wre.y;
        }
        float2 ts = sT[kyi];
        sZ[kyi * COUT + op]     = make_float2(ar0 * ts.x - ai0 * ts.y,
                                              ar0 * ts.y + ai0 * ts.x);
        sZ[kyi * COUT + op + 1] = make_float2(ar1 * ts.x - ai1 * ts.y,
                                              ar1 * ts.y + ai1 * ts.x);
    }
    // stage-3 packed table (aliases dead PA region, disjoint from sZ/sSD)
    for (int i = tid; i < 65 * 9; i += 288) T3p[i] = g_T2b[i];
    __syncthreads();

    // ---- S/D mode pairs: modes p=1..16 pair with (34-p); p=17 unpaired ----
    for (int i = tid; i < MM * 32; i += 288) {
        int p = (i >> 5) + 1, o = i & 31;
        float2 zp = sZ[p * COUT + o];
        float4 sd;
        if (p < MM) {
            float2 zq = sZ[(34 - p) * COUT + o];
            sd = make_float4(zp.x + zq.x, zp.y + zq.y, zp.x - zq.x, zp.y - zq.y);
        } else {
            sd = make_float4(zp.x, zp.y, -zp.x, -zp.y);
        }
        sSD[i] = sd;
    }
    __syncthreads();

    // ---- stage 3: TWO yy per iteration share SD loads; Y[y]=E+F, Y[128-y]=E-F
    {
        int o = tid & 31, q = tid >> 5;      // q 0..8
        float2 z0 = sZ[o];
        const float4* SD = &sSD[o];
        for (int yb = q * 2; yb <= 64; yb += 18) {
            int y2ok = (yb + 1 <= 64);
            const float4* Ta = &T3p[yb * 9];
            const float4* Tb = y2ok ? &T3p[(yb + 1) * 9] : Ta;
            float er1 = z0.x, ei1 = z0.y, fr1 = 0.f, fi1 = 0.f;
            float er2 = z0.x, ei2 = z0.y, fr2 = 0.f, fi2 = 0.f;
            #pragma unroll 2
            for (int j = 0; j < 8; ++j) {
                float4 a  = SD[(2 * j) * 32];
                float4 b2 = SD[(2 * j + 1) * 32];
                float4 wA = Ta[j];
                er1 += a.x * wA.x;   ei1 += a.y * wA.x;
                fr1 -= a.w * wA.y;   fi1 += a.z * wA.y;
                er1 += b2.x * wA.z;  ei1 += b2.y * wA.z;
                fr1 -= b2.w * wA.w;  fi1 += b2.z * wA.w;
                float4 wB = Tb[j];
                er2 += a.x * wB.x;   ei2 += a.y * wB.x;
                fr2 -= a.w * wB.y;   fi2 += a.z * wB.y;
                er2 += b2.x * wB.z;  ei2 += b2.y * wB.z;
                fr2 -= b2.w * wB.w;  fi2 += b2.z * wB.w;
            }
            {   // mode 17
                float4 a  = SD[16 * 32];
                float4 wA = Ta[8];
                er1 += a.x * wA.x;  ei1 += a.y * wA.x;
                fr1 -= a.w * wA.y;  fi1 += a.z * wA.y;
                float4 wB = Tb[8];
                er2 += a.x * wB.x;  ei2 += a.y * wB.x;
                fr2 -= a.w * wB.y;  fi2 += a.z * wB.y;
            }
            size_t rb = ((size_t)b * GRID_N) * MM * COUT + (size_t)kx * COUT + o;
            g_Y1[rb + (size_t)yb * MM * COUT] = make_float2(er1 + fr1, ei1 + fi1);
            if (yb >= 1 && yb < 64)
                g_Y1[rb + (size_t)(128 - yb) * MM * COUT] =
                    make_float2(er1 - fr1, ei1 - fi1);
            if (y2ok) {
                int y2 = yb + 1;                   // 1..63 -> both outputs
                g_Y1[rb + (size_t)y2 * MM * COUT] = make_float2(er2 + fr2, ei2 + fi2);
                g_Y1[rb + (size_t)(128 - y2) * MM * COUT] =
                    make_float2(er2 - fr2, ei2 - fi2);
            }
        }
    }
}

// ---------------------------------------------------------------------------
// K3: inverse over x (irfft C2R), output pairing, ONE y-row per block
// (register-light), float4-packed twiddles copied from gmem.
//   out[x] = E+O, out[128-x] = E-O
// ---------------------------------------------------------------------------
__global__ void __launch_bounds__(256) k3_idftx(float* __restrict__ out) {
    __shared__ float2 sY[MM * COUT];   // 4.25 KB
    __shared__ float4 T3[65 * 8];      // copied from g_T3
    int b = blockIdx.x >> 7, y = blockIdx.x & 127;
    int tid = threadIdx.x;

    const float2* src = g_Y1 + (size_t)(b * GRID_N + y) * MM * COUT;
    for (int i = tid; i < MM * COUT; i += 256) sY[i] = src[i];
    for (int i = tid; i < 65 * 8; i += 256) T3[i] = g_T3[i];
    __syncthreads();

    int o  = tid & 31;
    int xg = tid >> 5;   // 0..7

    float yr[MM], yi[MM];
    yr[0] = sY[o].x;     // Im of bin 0 ignored (C2R); bin 64 is zero
    yi[0] = 0.f;
    #pragma unroll
    for (int k = 1; k < MM; ++k) {
        float2 v = sY[k * COUT + o];
        yr[k] = 2.f * v.x;
        yi[k] = 2.f * v.y;
    }

    float* orow = out + (size_t)(b * GRID_N + y) * GRID_N * COUT;
    for (int xx = xg; xx <= 64; xx += 8) {
        float E = yr[0], O = 0.f;
        const float4* T = &T3[xx * 8];
        #pragma unroll
        for (int j = 0; j < 8; ++j) {
            float4 w = T[j];            // warp-uniform broadcast, imm offsets
            int ka = 2 * j + 1, kb = 2 * j + 2;
            E += yr[ka] * w.x;  O -= yi[ka] * w.y;
            E += yr[kb] * w.z;  O -= yi[kb] * w.w;
        }
        orow[(size_t)xx * COUT + o] = E + O;
        if (xx >= 1 && xx < 64)
            orow[(size_t)(128 - xx) * COUT + o] = E - O;
    }
}

// ---------------------------------------------------------------------------
extern "C" void kernel_launch(void* const* d_in, const int* in_sizes, int n_in,
                              void* d_out, int out_size) {
    const float* x     = (const float*)d_in[0];
    const float* t_emb = (const float*)d_in[1];
    const float* w1r   = (const float*)d_in[2];
    const float* w1i   = (const float*)d_in[3];
    const float* w2r   = (const float*)d_in[4];
    const float* w2i   = (const float*)d_in[5];
    const float* k1r   = (const float*)d_in[6];
    const float* k1i   = (const float*)d_in[7];
    const float* k2r   = (const float*)d_in[8];
    const float* k2i   = (const float*)d_in[9];
    float* out = (float*)d_out;

    cudaFuncSetAttribute(k2_mid, cudaFuncAttributeMaxDynamicSharedMemorySize,
                         K2_SMEM_BYTES);

    k0_setup<<<NB, 256>>>(t_emb, k1r, k1i, k2r, k2i);
    k1_dftx <<<NB * GRID_N, 288>>>(x);
    k2_mid  <<<NB * MM, 288, K2_SMEM_BYTES>>>(w1r, w1i, w2r, w2i);
    k3_idftx<<<NB * GRID_N, 256>>>(out);
}